// round 5
// baseline (speedup 1.0000x reference)
#include <cuda_runtime.h>
#include <cstdint>

#define B_  8
#define H_  512
#define W_  512
#define HW  (H_ * W_)
#define N_PIX (B_ * HW)          // 2,097,152
#define NV    (N_PIX / 4)        // 524,288 float4 chunks
#define EPS_  1e-10f

#define THREADS 256
#define BLOCKS  (NV / THREADS)   // 2048 — exactly one chunk per thread

// Device-global accumulator state (zero at module load; reset by the last
// block each launch so graph replays are deterministic).
__device__ float        g_acc;
__device__ unsigned int g_count;

__device__ __forceinline__ float clipf(float v) {
    return fminf(fmaxf(v, EPS_), 1.0f - EPS_);
}

__device__ __forceinline__ float warp_reduce(float v) {
    #pragma unroll
    for (int o = 16; o; o >>= 1) v += __shfl_xor_sync(0xffffffffu, v, o);
    return v;
}

// Sum over j of (p[j]-t[j])^2 * w[j], for one stream pair (float4 regs).
__device__ __forceinline__ float sq4(float4 p, const float* t, const float* w) {
    const float* pj = &p.x;
    float s = 0.0f;
    #pragma unroll
    for (int j = 0; j < 4; ++j) {
        float d = pj[j] - t[j];
        s += d * d * w[j];
    }
    return s;
}

__global__ __launch_bounds__(THREADS, 6)
void fused_loss_kernel(
    const float* __restrict__ roi,
    const float* __restrict__ hm0,  const float* __restrict__ hm1,
    const float* __restrict__ hm2,
    const float* __restrict__ r1pf, const float* __restrict__ r1pb,
    const float* __restrict__ r1nf, const float* __restrict__ r1nb,
    const float* __restrict__ r0f,  const float* __restrict__ r0b,
    const float* __restrict__ r2f,  const float* __restrict__ r2b,
    const float* __restrict__ f01f, const float* __restrict__ f10b,
    const float* __restrict__ f12f, const float* __restrict__ f21b,
    float* __restrict__ out)
{
    const int c = blockIdx.x * THREADS + threadIdx.x;   // chunk id, 0..NV-1
    float acc = 0.0f;

    // roi chunk shared by both phases.
    float4 m4 = __ldg((const float4*)roi + c);
    const float* mj = &m4.x;

    // ---------------- Phase A: reconstruction losses (grouped) -------------
    {
        float4 h04 = __ldg((const float4*)hm0 + c);
        float4 h14 = __ldg((const float4*)hm1 + c);
        float4 h24 = __ldg((const float4*)hm2 + c);
        const float* h0 = &h04.x;
        const float* h1 = &h14.x;
        const float* h2 = &h24.x;

        float wp[4], wn[4];
        #pragma unroll
        for (int j = 0; j < 4; ++j) {
            wp[j] = mj[j] * (1.0f + fabsf(h0[j] - h1[j]));
            wn[j] = mj[j] * (1.0f + fabsf(h1[j] - h2[j]));
        }

        // Group 1: targets h1 with weight wp
        float sA = sq4(__ldg((const float4*)r1pf + c), h1, wp)
                 + sq4(__ldg((const float4*)r1pb + c), h1, wp);
        // Group 2: targets h1 with weight wn
        float sB = sq4(__ldg((const float4*)r1nf + c), h1, wn)
                 + sq4(__ldg((const float4*)r1nb + c), h1, wn);
        // Group 3: targets h0 with weight wp
        float sC = sq4(__ldg((const float4*)r0f + c), h0, wp)
                 + sq4(__ldg((const float4*)r0b + c), h0, wp);
        // Group 4: targets h2 with weight wn
        float sD = sq4(__ldg((const float4*)r2f + c), h2, wn)
                 + sq4(__ldg((const float4*)r2b + c), h2, wn);

        acc += 0.25f * (sA + sB) + 0.50f * (sC + sD);
    }

    // ---------------- Phase B: flow consistency (4-wide chunks) ------------
    {
        const int pid = c * 4;
        const int b   = pid >> 18;            // / HW
        const int rem = pid & (HW - 1);
        const int y   = rem >> 9;             // / W
        const int x0  = rem & (W_ - 1);       // multiple of 4

        const size_t base_b = (size_t)b * 9 * HW;
        const size_t rowF   = base_b + (size_t)y * W_ + x0;

        float s[4] = {0.f, 0.f, 0.f, 0.f};

        const float* FW[2] = { f01f, f12f };
        const float* IV[2] = { f10b, f21b };

        #pragma unroll
        for (int p = 0; p < 2; ++p) {
            const float* F = FW[p];
            const float* I = IV[p];
            #pragma unroll
            for (int i = 0; i < 9; ++i) {
                const int dy = (i < 3) ? 1 : (i < 6) ? 0 : -1;
                const int mm = i % 3;
                const int dx = (mm == 0) ? 1 : (mm == 1) ? 0 : -1;

                const int yy = y - dy;
                if ((unsigned)yy >= (unsigned)H_) continue;

                float4 fv = __ldg((const float4*)(F + rowF + (size_t)i * HW));
                const float* fj = &fv.x;
                const float* Irow = I + base_b + (size_t)(8 - i) * HW
                                      + (size_t)yy * W_;

                if (dx == 0) {
                    float4 iv = __ldg((const float4*)(Irow + x0));
                    const float* ij = &iv.x;
                    #pragma unroll
                    for (int j = 0; j < 4; ++j) {
                        float d = clipf(fj[j]) - clipf(ij[j]);
                        s[j] += d * d;
                    }
                } else {
                    #pragma unroll
                    for (int j = 0; j < 4; ++j) {
                        const int xx = x0 + j - dx;
                        if ((unsigned)xx < (unsigned)W_) {
                            float d = clipf(fj[j]) - clipf(__ldg(Irow + xx));
                            s[j] += d * d;
                        }
                    }
                }
            }
        }

        acc += (1.0f / 9.0f) * (mj[0]*s[0] + mj[1]*s[1]
                              + mj[2]*s[2] + mj[3]*s[3]);
    }

    // ---------------- Block reduction + last-block finalize -----------------
    __shared__ float smem[THREADS / 32];
    float v = warp_reduce(acc);
    const int lane = threadIdx.x & 31;
    const int w    = threadIdx.x >> 5;
    if (lane == 0) smem[w] = v;
    __syncthreads();
    if (w == 0) {
        v = (lane < THREADS / 32) ? smem[lane] : 0.0f;
        v = warp_reduce(v);
        if (lane == 0) {
            atomicAdd(&g_acc, v);
            __threadfence();
            unsigned ticket = atomicAdd(&g_count, 1u);
            if (ticket == gridDim.x - 1) {
                float total = atomicExch(&g_acc, 0.0f);   // read + reset
                out[0] = total;
                atomicExch(&g_count, 0u);                 // reset for next replay
            }
        }
    }
}

extern "C" void kernel_launch(void* const* d_in, const int* in_sizes, int n_in,
                              void* d_out, int out_size)
{
    const float* roi  = (const float*)d_in[0];
    // d_in[1] = boundary_mask (unused by the reference)
    const float* hm0  = (const float*)d_in[2];
    const float* hm1  = (const float*)d_in[3];
    const float* hm2  = (const float*)d_in[4];
    const float* r1pf = (const float*)d_in[5];
    const float* r1pb = (const float*)d_in[6];
    const float* r1nf = (const float*)d_in[7];
    const float* r1nb = (const float*)d_in[8];
    const float* r0f  = (const float*)d_in[9];
    const float* r0b  = (const float*)d_in[10];
    const float* r2f  = (const float*)d_in[11];
    const float* r2b  = (const float*)d_in[12];
    const float* f01f = (const float*)d_in[13];
    const float* f10b = (const float*)d_in[14];
    const float* f12f = (const float*)d_in[15];
    const float* f21b = (const float*)d_in[16];

    fused_loss_kernel<<<BLOCKS, THREADS>>>(
        roi, hm0, hm1, hm2,
        r1pf, r1pb, r1nf, r1nb, r0f, r0b, r2f, r2b,
        f01f, f10b, f12f, f21b,
        (float*)d_out);
}

// round 6
// speedup vs baseline: 1.0306x; 1.0306x over previous
#include <cuda_runtime.h>
#include <cstdint>

#define B_  8
#define H_  512
#define W_  512
#define HW  (H_ * W_)
#define N_PIX (B_ * HW)          // 2,097,152
#define NV    (N_PIX / 4)        // 524,288 float4 chunks
#define EPS_  1e-10f

#define THREADS 256
#define BLOCKS  (NV / THREADS)   // 2048 — one chunk per thread

// Device-global accumulator state (zero at module load; reset by the last
// block each launch so graph replays are deterministic).
__device__ float        g_acc;
__device__ unsigned int g_count;

__device__ __forceinline__ float clipf(float v) {
    return fminf(fmaxf(v, EPS_), 1.0f - EPS_);
}

__device__ __forceinline__ float warp_reduce(float v) {
    #pragma unroll
    for (int o = 16; o; o >>= 1) v += __shfl_xor_sync(0xffffffffu, v, o);
    return v;
}

__global__ __launch_bounds__(THREADS)
void fused_loss_kernel(
    const float* __restrict__ roi,
    const float* __restrict__ hm0,  const float* __restrict__ hm1,
    const float* __restrict__ hm2,
    const float* __restrict__ r1pf, const float* __restrict__ r1pb,
    const float* __restrict__ r1nf, const float* __restrict__ r1nb,
    const float* __restrict__ r0f,  const float* __restrict__ r0b,
    const float* __restrict__ r2f,  const float* __restrict__ r2b,
    const float* __restrict__ f01f, const float* __restrict__ f10b,
    const float* __restrict__ f12f, const float* __restrict__ f21b,
    float* __restrict__ out)
{
    const int tid  = blockIdx.x * THREADS + threadIdx.x;   // chunk id 0..NV-1
    const int lane = threadIdx.x & 31;
    float acc = 0.0f;

    // ---------------- Phase A: reconstruction losses (R3 batched form) -----
    {
        const int i = tid;
        float4 m4  = ((const float4*)roi )[i];
        float4 h04 = ((const float4*)hm0 )[i];
        float4 h14 = ((const float4*)hm1 )[i];
        float4 h24 = ((const float4*)hm2 )[i];
        float4 a4  = ((const float4*)r1pf)[i];
        float4 b4  = ((const float4*)r1pb)[i];
        float4 c4  = ((const float4*)r1nf)[i];
        float4 d4  = ((const float4*)r1nb)[i];
        float4 e4  = ((const float4*)r0f )[i];
        float4 f4  = ((const float4*)r0b )[i];
        float4 g4  = ((const float4*)r2f )[i];
        float4 k4  = ((const float4*)r2b )[i];

        const float* m  = &m4.x;
        const float* h0 = &h04.x; const float* h1 = &h14.x; const float* h2 = &h24.x;
        const float* pa = &a4.x;  const float* pb = &b4.x;
        const float* pc = &c4.x;  const float* pd = &d4.x;
        const float* pe = &e4.x;  const float* pf = &f4.x;
        const float* pg = &g4.x;  const float* pk = &k4.x;

        #pragma unroll
        for (int j = 0; j < 4; ++j) {
            float pre  = fabsf(h0[j] - h1[j]);
            float post = fabsf(h1[j] - h2[j]);
            float wp = m[j] * (1.0f + pre);
            float wn = m[j] * (1.0f + post);

            float a = pa[j] - h1[j], b = pb[j] - h1[j];
            float c = pc[j] - h1[j], d = pd[j] - h1[j];
            float e = pe[j] - h0[j], f = pf[j] - h0[j];
            float g = pg[j] - h2[j], k = pk[j] - h2[j];

            acc += 0.25f * ((a*a + b*b) * wp + (c*c + d*d) * wn)
                 + 0.50f * ((e*e + f*f) * wp + (g*g + k*k) * wn);
        }
    }

    // ---------------- Phase B: flow consistency (shfl-assisted shifts) -----
    {
        const int c   = tid;
        const int pid = c * 4;
        const int b   = pid >> 18;            // / HW
        const int rem = pid & (HW - 1);
        const int y   = rem >> 9;             // warp-uniform (4 warps per row)
        const int x0  = rem & (W_ - 1);       // multiple of 4, consecutive in warp

        float4 m4 = ((const float4*)roi)[c];  // L1 hit (loaded in phase A)
        const float* mj = &m4.x;

        const size_t base_b = (size_t)b * 9 * HW;
        const size_t rowF   = base_b + (size_t)y * W_ + x0;

        float s[4] = {0.f, 0.f, 0.f, 0.f};

        const float* FW[2] = { f01f, f12f };
        const float* IV[2] = { f10b, f21b };

        #pragma unroll
        for (int p = 0; p < 2; ++p) {
            const float* F = FW[p];
            const float* I = IV[p];
            #pragma unroll
            for (int i = 0; i < 9; ++i) {
                const int dy = (i < 3) ? 1 : (i < 6) ? 0 : -1;
                const int mm = i % 3;
                const int dx = (mm == 0) ? 1 : (mm == 1) ? 0 : -1;

                const int yy = y - dy;                 // warp-uniform predicate
                if ((unsigned)yy >= (unsigned)H_) continue;

                float4 fv = *(const float4*)(F + rowF + (size_t)i * HW);
                const float* fj = &fv.x;
                const float* Irow = I + base_b + (size_t)(8 - i) * HW
                                      + (size_t)yy * W_;

                float4 iv = *(const float4*)(Irow + x0);

                if (dx == 0) {
                    const float* ij = &iv.x;
                    #pragma unroll
                    for (int j = 0; j < 4; ++j) {
                        float d = clipf(fj[j]) - clipf(ij[j]);
                        s[j] += d * d;
                    }
                } else if (dx == 1) {
                    // need Irow[x0-1 .. x0+2] = {prev, iv.x, iv.y, iv.z}
                    float prev = __shfl_up_sync(0xffffffffu, iv.w, 1);
                    if (lane == 0 && x0 > 0) prev = Irow[x0 - 1];
                    if (x0 > 0) {                      // xx = x0-1 >= 0
                        float d = clipf(fj[0]) - clipf(prev);
                        s[0] += d * d;
                    }
                    {
                        float d1 = clipf(fj[1]) - clipf(iv.x);
                        float d2 = clipf(fj[2]) - clipf(iv.y);
                        float d3 = clipf(fj[3]) - clipf(iv.z);
                        s[1] += d1 * d1; s[2] += d2 * d2; s[3] += d3 * d3;
                    }
                } else { // dx == -1
                    // need Irow[x0+1 .. x0+4] = {iv.y, iv.z, iv.w, next}
                    float nxt = __shfl_down_sync(0xffffffffu, iv.x, 1);
                    if (lane == 31 && x0 < W_ - 4) nxt = Irow[x0 + 4];
                    {
                        float d0 = clipf(fj[0]) - clipf(iv.y);
                        float d1 = clipf(fj[1]) - clipf(iv.z);
                        float d2 = clipf(fj[2]) - clipf(iv.w);
                        s[0] += d0 * d0; s[1] += d1 * d1; s[2] += d2 * d2;
                    }
                    if (x0 < W_ - 4) {                 // xx = x0+4 <= 511
                        float d = clipf(fj[3]) - clipf(nxt);
                        s[3] += d * d;
                    }
                }
            }
        }

        acc += (1.0f / 9.0f) * (mj[0]*s[0] + mj[1]*s[1]
                              + mj[2]*s[2] + mj[3]*s[3]);
    }

    // ---------------- Block reduction + last-block finalize -----------------
    __shared__ float smem[THREADS / 32];
    float v = warp_reduce(acc);
    const int w = threadIdx.x >> 5;
    if (lane == 0) smem[w] = v;
    __syncthreads();
    if (w == 0) {
        v = (lane < THREADS / 32) ? smem[lane] : 0.0f;
        v = warp_reduce(v);
        if (lane == 0) {
            atomicAdd(&g_acc, v);
            __threadfence();
            unsigned ticket = atomicAdd(&g_count, 1u);
            if (ticket == gridDim.x - 1) {
                float total = atomicExch(&g_acc, 0.0f);   // read + reset
                out[0] = total;
                atomicExch(&g_count, 0u);                 // reset for next replay
            }
        }
    }
}

extern "C" void kernel_launch(void* const* d_in, const int* in_sizes, int n_in,
                              void* d_out, int out_size)
{
    const float* roi  = (const float*)d_in[0];
    // d_in[1] = boundary_mask (unused by the reference)
    const float* hm0  = (const float*)d_in[2];
    const float* hm1  = (const float*)d_in[3];
    const float* hm2  = (const float*)d_in[4];
    const float* r1pf = (const float*)d_in[5];
    const float* r1pb = (const float*)d_in[6];
    const float* r1nf = (const float*)d_in[7];
    const float* r1nb = (const float*)d_in[8];
    const float* r0f  = (const float*)d_in[9];
    const float* r0b  = (const float*)d_in[10];
    const float* r2f  = (const float*)d_in[11];
    const float* r2b  = (const float*)d_in[12];
    const float* f01f = (const float*)d_in[13];
    const float* f10b = (const float*)d_in[14];
    const float* f12f = (const float*)d_in[15];
    const float* f21b = (const float*)d_in[16];

    fused_loss_kernel<<<BLOCKS, THREADS>>>(
        roi, hm0, hm1, hm2,
        r1pf, r1pb, r1nf, r1nb, r0f, r0b, r2f, r2b,
        f01f, f10b, f12f, f21b,
        (float*)d_out);
}

// round 8
// speedup vs baseline: 1.1621x; 1.1276x over previous
#include <cuda_runtime.h>
#include <cstdint>

#define B_  8
#define H_  512
#define W_  512
#define HW  (H_ * W_)
#define N_PIX (B_ * HW)          // 2,097,152
#define NV    (N_PIX / 4)        // 524,288 float4 chunks
#define EPS_  1e-10f

#define THREADS 128
#define BLOCKS  (NV / THREADS)   // 4096 — one chunk per thread, fine-grained tail

// Device-global accumulator state (zero at module load; reset by the last
// block each launch so graph replays are deterministic).
__device__ float        g_acc;
__device__ unsigned int g_count;

__device__ __forceinline__ float clipf(float v) {
    return fminf(fmaxf(v, EPS_), 1.0f - EPS_);
}

__device__ __forceinline__ float warp_reduce(float v) {
    #pragma unroll
    for (int o = 16; o; o >>= 1) v += __shfl_xor_sync(0xffffffffu, v, o);
    return v;
}

__global__ __launch_bounds__(THREADS)
void fused_loss_kernel(
    const float* __restrict__ roi,
    const float* __restrict__ hm0,  const float* __restrict__ hm1,
    const float* __restrict__ hm2,
    const float* __restrict__ r1pf, const float* __restrict__ r1pb,
    const float* __restrict__ r1nf, const float* __restrict__ r1nb,
    const float* __restrict__ r0f,  const float* __restrict__ r0b,
    const float* __restrict__ r2f,  const float* __restrict__ r2b,
    const float* __restrict__ f01f, const float* __restrict__ f10b,
    const float* __restrict__ f12f, const float* __restrict__ f21b,
    float* __restrict__ out)
{
    const int tid = blockIdx.x * THREADS + threadIdx.x;   // chunk id 0..NV-1
    float acc = 0.0f;

    // roi chunk: loaded once, used by both phases.
    float4 m4 = ((const float4*)roi)[tid];
    const float* mj = &m4.x;

    // ---------------- Phase A: reconstruction losses (batched loads) -------
    {
        const int i = tid;
        float4 h04 = ((const float4*)hm0 )[i];
        float4 h14 = ((const float4*)hm1 )[i];
        float4 h24 = ((const float4*)hm2 )[i];
        float4 a4  = ((const float4*)r1pf)[i];
        float4 b4  = ((const float4*)r1pb)[i];
        float4 c4  = ((const float4*)r1nf)[i];
        float4 d4  = ((const float4*)r1nb)[i];
        float4 e4  = ((const float4*)r0f )[i];
        float4 f4  = ((const float4*)r0b )[i];
        float4 g4  = ((const float4*)r2f )[i];
        float4 k4  = ((const float4*)r2b )[i];

        const float* h0 = &h04.x; const float* h1 = &h14.x; const float* h2 = &h24.x;
        const float* pa = &a4.x;  const float* pb = &b4.x;
        const float* pc = &c4.x;  const float* pd = &d4.x;
        const float* pe = &e4.x;  const float* pf = &f4.x;
        const float* pg = &g4.x;  const float* pk = &k4.x;

        #pragma unroll
        for (int j = 0; j < 4; ++j) {
            float pre  = fabsf(h0[j] - h1[j]);
            float post = fabsf(h1[j] - h2[j]);
            float wp = mj[j] * (1.0f + pre);
            float wn = mj[j] * (1.0f + post);

            float a = pa[j] - h1[j], b = pb[j] - h1[j];
            float c = pc[j] - h1[j], d = pd[j] - h1[j];
            float e = pe[j] - h0[j], f = pf[j] - h0[j];
            float g = pg[j] - h2[j], k = pk[j] - h2[j];

            acc += 0.25f * ((a*a + b*b) * wp + (c*c + d*d) * wn)
                 + 0.50f * ((e*e + f*f) * wp + (g*g + k*k) * wn);
        }
    }

    // ---------------- Phase B: flow consistency (4-wide chunks) ------------
    {
        const int c   = tid;
        const int pid = c * 4;
        const int b   = pid >> 18;            // / HW
        const int rem = pid & (HW - 1);
        const int y   = rem >> 9;             // / W
        const int x0  = rem & (W_ - 1);       // multiple of 4

        const size_t base_b = (size_t)b * 9 * HW;
        const size_t rowF   = base_b + (size_t)y * W_ + x0;

        float s[4] = {0.f, 0.f, 0.f, 0.f};

        const float* FW[2] = { f01f, f12f };
        const float* IV[2] = { f10b, f21b };

        #pragma unroll
        for (int p = 0; p < 2; ++p) {
            const float* F = FW[p];
            const float* I = IV[p];
            #pragma unroll
            for (int i = 0; i < 9; ++i) {
                const int dy = (i < 3) ? 1 : (i < 6) ? 0 : -1;
                const int mm = i % 3;
                const int dx = (mm == 0) ? 1 : (mm == 1) ? 0 : -1;

                const int yy = y - dy;
                if ((unsigned)yy >= (unsigned)H_) continue;

                float4 fv = *(const float4*)(F + rowF + (size_t)i * HW);
                const float* fj = &fv.x;
                const float* Irow = I + base_b + (size_t)(8 - i) * HW
                                      + (size_t)yy * W_;

                if (dx == 0) {
                    float4 iv = *(const float4*)(Irow + x0);
                    const float* ij = &iv.x;
                    #pragma unroll
                    for (int j = 0; j < 4; ++j) {
                        float d = clipf(fj[j]) - clipf(ij[j]);
                        s[j] += d * d;
                    }
                } else {
                    #pragma unroll
                    for (int j = 0; j < 4; ++j) {
                        const int xx = x0 + j - dx;
                        if ((unsigned)xx < (unsigned)W_) {
                            float d = clipf(fj[j]) - clipf(Irow[xx]);
                            s[j] += d * d;
                        }
                    }
                }
            }
        }

        acc += (1.0f / 9.0f) * (mj[0]*s[0] + mj[1]*s[1]
                              + mj[2]*s[2] + mj[3]*s[3]);
    }

    // ---------------- Block reduction + last-block finalize -----------------
    __shared__ float smem[THREADS / 32];
    float v = warp_reduce(acc);
    const int lane = threadIdx.x & 31;
    const int w    = threadIdx.x >> 5;
    if (lane == 0) smem[w] = v;
    __syncthreads();
    if (w == 0) {
        v = (lane < THREADS / 32) ? smem[lane] : 0.0f;
        v = warp_reduce(v);
        if (lane == 0) {
            atomicAdd(&g_acc, v);
            __threadfence();
            unsigned ticket = atomicAdd(&g_count, 1u);
            if (ticket == gridDim.x - 1) {
                float total = atomicExch(&g_acc, 0.0f);   // read + reset
                out[0] = total;
                atomicExch(&g_count, 0u);                 // reset for next replay
            }
        }
    }
}

extern "C" void kernel_launch(void* const* d_in, const int* in_sizes, int n_in,
                              void* d_out, int out_size)
{
    const float* roi  = (const float*)d_in[0];
    // d_in[1] = boundary_mask (unused by the reference)
    const float* hm0  = (const float*)d_in[2];
    const float* hm1  = (const float*)d_in[3];
    const float* hm2  = (const float*)d_in[4];
    const float* r1pf = (const float*)d_in[5];
    const float* r1pb = (const float*)d_in[6];
    const float* r1nf = (const float*)d_in[7];
    const float* r1nb = (const float*)d_in[8];
    const float* r0f  = (const float*)d_in[9];
    const float* r0b  = (const float*)d_in[10];
    const float* r2f  = (const float*)d_in[11];
    const float* r2b  = (const float*)d_in[12];
    const float* f01f = (const float*)d_in[13];
    const float* f10b = (const float*)d_in[14];
    const float* f12f = (const float*)d_in[15];
    const float* f21b = (const float*)d_in[16];

    fused_loss_kernel<<<BLOCKS, THREADS>>>(
        roi, hm0, hm1, hm2,
        r1pf, r1pb, r1nf, r1nb, r0f, r0b, r2f, r2b,
        f01f, f10b, f12f, f21b,
        (float*)d_out);
}